// round 1
// baseline (speedup 1.0000x reference)
#include <cuda_runtime.h>

// Masked dense 3D conv: out[b,co,d,h,w] = mask[b,d,h,w] * (bias[co] + sum_{ci,kd,kh,kw} x[b,ci,d+kd-1,h+kh-1,w+kw-1]*W[co,ci,kd,kh,kw])
// B=2, CI=32, CO=64, K=3, D=H=W=96, SAME padding.

#define CI_   32
#define CO_   64
#define NVOX  96
#define THT   8     // H tile
#define TWT   32    // W tile
#define CICH  4     // CI chunk
#define XS_ELEMS (CICH*3*10*34)        // 4080
#define WS_R     (CICH*27)             // 108
#define WS_STRIDE 65                    // padded: (r+co)%32 conflict-free
#define WS_ELEMS (WS_R*WS_STRIDE)      // 7020

__global__ __launch_bounds__(256, 2)
void sparse_conv3d_fp32_kernel(const float* __restrict__ x,
                               const int*   __restrict__ mask,
                               const float* __restrict__ wgt,
                               const float* __restrict__ bias,
                               float*       __restrict__ out)
{
    __shared__ float xs[XS_ELEMS];
    __shared__ float ws[WS_ELEMS];
    __shared__ float bs[CO_];

    const int t  = threadIdx.x;
    const int bz = blockIdx.z;           // b*96 + d
    const int b  = bz / NVOX;
    const int d  = bz % NVOX;
    const int h0 = blockIdx.y * THT;
    const int w0 = blockIdx.x * TWT;

    if (t < CO_) bs[t] = bias[t];

    const int cg    = t >> 6;            // co group 0..3 (16 co each)
    const int sp    = t & 63;            // spatial thread 0..63
    const int hg    = sp >> 5;           // 0..1
    const int wl    = sp & 31;           // 0..31
    const int hbase = hg * 4;            // thread covers h = hbase..hbase+3

    float acc[4][16];
    #pragma unroll
    for (int i = 0; i < 4; i++)
        #pragma unroll
        for (int j = 0; j < 16; j++)
            acc[i][j] = 0.0f;

    for (int chunk = 0; chunk < CI_ / CICH; chunk++) {
        const int ci0 = chunk * CICH;
        __syncthreads();  // protect smem being overwritten (also fences bs on first iter)

        // --- load x tile: [ci_l][dz][y(10)][xw(34)], zero-padded at borders ---
        for (int f = t; f < XS_ELEMS; f += 256) {
            int ci_l = f / (3*10*34);
            int rem  = f % (3*10*34);
            int dz   = rem / (10*34);
            int rem2 = rem % (10*34);
            int yy   = rem2 / 34;
            int xx   = rem2 % 34;
            int gd = d  + dz - 1;
            int gh = h0 + yy - 1;
            int gw = w0 + xx - 1;
            float v = 0.0f;
            if ((unsigned)gd < (unsigned)NVOX &&
                (unsigned)gh < (unsigned)NVOX &&
                (unsigned)gw < (unsigned)NVOX) {
                v = x[(((b*CI_ + ci0 + ci_l)*NVOX + gd)*NVOX + gh)*NVOX + gw];
            }
            xs[f] = v;
        }

        // --- load weight slice: global [co][ci][tap] -> smem ws[r*65 + co] ---
        // coalesced global reads (r runs contiguous within a co), conflict-free STS (stride 65)
        for (int f = t; f < CICH*27*CO_; f += 256) {
            int co = f / WS_R;
            int r  = f % WS_R;
            ws[r*WS_STRIDE + co] = wgt[co*(CI_*27) + ci0*27 + r];
        }
        __syncthreads();

        // --- compute: per (ci_l, tap): 16 broadcast weight LDS + 4 x LDS -> 64 FFMA ---
        #pragma unroll 1
        for (int ci_l = 0; ci_l < CICH; ci_l++) {
            #pragma unroll 1
            for (int kd = 0; kd < 3; kd++) {
                const float* xsd = &xs[(ci_l*3 + kd) * (10*34)];
                const int rbase = ci_l*27 + kd*9;
                #pragma unroll
                for (int kh = 0; kh < 3; kh++) {
                    #pragma unroll
                    for (int kw = 0; kw < 3; kw++) {
                        const int r = rbase + kh*3 + kw;
                        float wv[16];
                        #pragma unroll
                        for (int j = 0; j < 16; j++)
                            wv[j] = ws[r*WS_STRIDE + cg*16 + j];
                        #pragma unroll
                        for (int i = 0; i < 4; i++) {
                            float xv = xsd[(hbase + i + kh)*34 + wl + kw];
                            #pragma unroll
                            for (int j = 0; j < 16; j++)
                                acc[i][j] += xv * wv[j];
                        }
                    }
                }
            }
        }
    }

    // --- epilogue: bias + mask, coalesced stores ---
    const int gw = w0 + wl;
    #pragma unroll
    for (int i = 0; i < 4; i++) {
        const int gh = h0 + hbase + i;
        const float mf = (float)mask[((b*NVOX + d)*NVOX + gh)*NVOX + gw];
        #pragma unroll
        for (int j = 0; j < 16; j++) {
            const int co = cg*16 + j;
            out[(((b*CO_ + co)*NVOX + d)*NVOX + gh)*NVOX + gw] =
                (acc[i][j] + bs[co]) * mf;
        }
    }
}

extern "C" void kernel_launch(void* const* d_in, const int* in_sizes, int n_in,
                              void* d_out, int out_size)
{
    const float* x    = (const float*)d_in[0];
    const int*   mask = (const int*)  d_in[1];
    const float* wgt  = (const float*)d_in[2];
    const float* bias = (const float*)d_in[3];
    float* out = (float*)d_out;

    dim3 grid(NVOX/TWT, NVOX/THT, 2*NVOX);  // (3, 12, 192)
    sparse_conv3d_fp32_kernel<<<grid, 256>>>(x, mask, wgt, bias, out);
}

// round 2
// speedup vs baseline: 1.0003x; 1.0003x over previous
#include <cuda_runtime.h>

// Masked dense 3D conv: out[b,co,d,h,w] = mask[b,d,h,w] * (bias[co] + sum_{ci,kd,kh,kw} x[b,ci,d+kd-1,h+kh-1,w+kw-1]*W[co,ci,kd,kh,kw])
// B=2, CI=32, CO=64, K=3, D=H=W=96, SAME padding.

#define CI_   32
#define CO_   64
#define NVOX  96
#define THT   8     // H tile
#define TWT   32    // W tile
#define CICH  4     // CI chunk
#define XS_ELEMS (CICH*3*10*34)        // 4080
#define WS_R     (CICH*27)             // 108
#define WS_STRIDE 65                    // padded: (r+co)%32 conflict-free
#define WS_ELEMS (WS_R*WS_STRIDE)      // 7020

__global__ __launch_bounds__(256, 2)
void sparse_conv3d_fp32_kernel(const float* __restrict__ x,
                               const int*   __restrict__ mask,
                               const float* __restrict__ wgt,
                               const float* __restrict__ bias,
                               float*       __restrict__ out)
{
    __shared__ float xs[XS_ELEMS];
    __shared__ float ws[WS_ELEMS];
    __shared__ float bs[CO_];

    const int t  = threadIdx.x;
    const int bz = blockIdx.z;           // b*96 + d
    const int b  = bz / NVOX;
    const int d  = bz % NVOX;
    const int h0 = blockIdx.y * THT;
    const int w0 = blockIdx.x * TWT;

    if (t < CO_) bs[t] = bias[t];

    const int cg    = t >> 6;            // co group 0..3 (16 co each)
    const int sp    = t & 63;            // spatial thread 0..63
    const int hg    = sp >> 5;           // 0..1
    const int wl    = sp & 31;           // 0..31
    const int hbase = hg * 4;            // thread covers h = hbase..hbase+3

    float acc[4][16];
    #pragma unroll
    for (int i = 0; i < 4; i++)
        #pragma unroll
        for (int j = 0; j < 16; j++)
            acc[i][j] = 0.0f;

    for (int chunk = 0; chunk < CI_ / CICH; chunk++) {
        const int ci0 = chunk * CICH;
        __syncthreads();  // protect smem being overwritten (also fences bs on first iter)

        // --- load x tile: [ci_l][dz][y(10)][xw(34)], zero-padded at borders ---
        for (int f = t; f < XS_ELEMS; f += 256) {
            int ci_l = f / (3*10*34);
            int rem  = f % (3*10*34);
            int dz   = rem / (10*34);
            int rem2 = rem % (10*34);
            int yy   = rem2 / 34;
            int xx   = rem2 % 34;
            int gd = d  + dz - 1;
            int gh = h0 + yy - 1;
            int gw = w0 + xx - 1;
            float v = 0.0f;
            if ((unsigned)gd < (unsigned)NVOX &&
                (unsigned)gh < (unsigned)NVOX &&
                (unsigned)gw < (unsigned)NVOX) {
                v = x[(((b*CI_ + ci0 + ci_l)*NVOX + gd)*NVOX + gh)*NVOX + gw];
            }
            xs[f] = v;
        }

        // --- load weight slice: global [co][ci][tap] -> smem ws[r*65 + co] ---
        // coalesced global reads (r runs contiguous within a co), conflict-free STS (stride 65)
        for (int f = t; f < CICH*27*CO_; f += 256) {
            int co = f / WS_R;
            int r  = f % WS_R;
            ws[r*WS_STRIDE + co] = wgt[co*(CI_*27) + ci0*27 + r];
        }
        __syncthreads();

        // --- compute: per (ci_l, tap): 16 broadcast weight LDS + 4 x LDS -> 64 FFMA ---
        #pragma unroll 1
        for (int ci_l = 0; ci_l < CICH; ci_l++) {
            #pragma unroll 1
            for (int kd = 0; kd < 3; kd++) {
                const float* xsd = &xs[(ci_l*3 + kd) * (10*34)];
                const int rbase = ci_l*27 + kd*9;
                #pragma unroll
                for (int kh = 0; kh < 3; kh++) {
                    #pragma unroll
                    for (int kw = 0; kw < 3; kw++) {
                        const int r = rbase + kh*3 + kw;
                        float wv[16];
                        #pragma unroll
                        for (int j = 0; j < 16; j++)
                            wv[j] = ws[r*WS_STRIDE + cg*16 + j];
                        #pragma unroll
                        for (int i = 0; i < 4; i++) {
                            float xv = xsd[(hbase + i + kh)*34 + wl + kw];
                            #pragma unroll
                            for (int j = 0; j < 16; j++)
                                acc[i][j] += xv * wv[j];
                        }
                    }
                }
            }
        }
    }

    // --- epilogue: bias + mask, coalesced stores ---
    const int gw = w0 + wl;
    #pragma unroll
    for (int i = 0; i < 4; i++) {
        const int gh = h0 + hbase + i;
        const float mf = (float)mask[((b*NVOX + d)*NVOX + gh)*NVOX + gw];
        #pragma unroll
        for (int j = 0; j < 16; j++) {
            const int co = cg*16 + j;
            out[(((b*CO_ + co)*NVOX + d)*NVOX + gh)*NVOX + gw] =
                (acc[i][j] + bs[co]) * mf;
        }
    }
}

extern "C" void kernel_launch(void* const* d_in, const int* in_sizes, int n_in,
                              void* d_out, int out_size)
{
    const float* x    = (const float*)d_in[0];
    const int*   mask = (const int*)  d_in[1];
    const float* wgt  = (const float*)d_in[2];
    const float* bias = (const float*)d_in[3];
    float* out = (float*)d_out;

    dim3 grid(NVOX/TWT, NVOX/THT, 2*NVOX);  // (3, 12, 192)
    sparse_conv3d_fp32_kernel<<<grid, 256>>>(x, mask, wgt, bias, out);
}

// round 6
// speedup vs baseline: 2.0679x; 2.0673x over previous
#include <cuda_runtime.h>
#include <cstdint>

// SparseConv3d as implicit GEMM via mma.sync tf32 (sm_80+ path; tcgen05 not
// available on this toolchain's .target sm_103).
// out[b,co,d,h,w] = mask * (bias[co] + sum_{ci,kd,kh,kw} x*W), B=2 CI=32 CO=64 K=3 96^3.

#define NV      96
#define NV2     (NV*NV)          // 9216
#define NV3     (NV*NV2)
#define CI_     32
#define CO_     64
#define ROWW    98
#define PLANE_Q (NV*ROWW)        // 9408
#define MT      128
#define NTILES  74               // ceil(9408/128)
#define S_STR   328              // scratch row stride (mod 32 == 8 -> conflict-free A frags)
#define S_ROWS  326
#define EP_STR  66

// weight fragments: [tap][gnt(8)][ks(4)][lane(32)] as float2 (b0,b1)
__device__ float2 g_wfrag[27 * 8 * 4 * 32];

__device__ __forceinline__ uint32_t f2tf32(float f) {
    uint32_t r; asm("cvt.rna.tf32.f32 %0, %1;" : "=r"(r) : "f"(f)); return r;
}

// ---------------- weight prep: -> tf32 B-fragment order ----------------
extern "C" __global__ void wprep_kernel(const float* __restrict__ wgt) {
    int idx = blockIdx.x * 256 + threadIdx.x;   // over 27*8*4*32 float2
    if (idx >= 27 * 8 * 4 * 32) return;
    int lane = idx & 31;
    int r    = idx >> 5;
    int ks   = r & 3;  r >>= 2;
    int gnt  = r & 7;  r >>= 3;
    int tap  = r;
    int g = lane >> 2, t = lane & 3;
    int co  = gnt * 8 + g;
    int ci0 = ks * 8 + t;          // b0: k = t
    int ci1 = ci0 + 4;             // b1: k = t+4
    float2 v;
    v.x = __uint_as_float(f2tf32(wgt[(co * CI_ + ci0) * 27 + tap]));
    v.y = __uint_as_float(f2tf32(wgt[(co * CI_ + ci1) * 27 + tap]));
    g_wfrag[idx] = v;
}

// ---------------- main kernel ----------------
extern "C" __global__ void __launch_bounds__(256, 2)
conv_mma_kernel(const float* __restrict__ x, const int* __restrict__ mask,
                const float* __restrict__ bias, float* __restrict__ out)
{
    __shared__ float scratch[CI_ * S_STR];   // 41984 B; reused as epilogue [128][66]
    __shared__ float bs[CO_];

    const int tid  = threadIdx.x;
    const int w    = tid >> 5;
    const int lane = tid & 31;
    const int g    = lane >> 2;
    const int t    = lane & 3;

    const int tile = blockIdx.x;
    const int pz   = blockIdx.y;              // b*96 + d
    const int b = pz / NV, d = pz % NV;
    const int q0   = tile * MT;
    const int q_lo = q0 - 99;

    const int warp_m = (w >> 1) * 32;         // 0,32,64,96
    const int warp_n = (w & 1) * 32;          // 0,32

    if (tid < CO_) bs[tid] = bias[tid];

    float acc[2][4][4];
    #pragma unroll
    for (int mt = 0; mt < 2; mt++)
        #pragma unroll
        for (int nt = 0; nt < 4; nt++)
            #pragma unroll
            for (int c = 0; c < 4; c++) acc[mt][nt][c] = 0.0f;

    const uint32_t* scr_u = (const uint32_t*)scratch;

    for (int dz = 0; dz < 3; dz++) {
        const int dcur = d + dz - 1;
        const int dok  = ((unsigned)dcur < (unsigned)NV);
        __syncthreads();   // all warps done reading previous dz's scratch

        // ---- fill scratch [ci][s]: tf32 bits, zero outside plane / pad cols ----
        for (int idx = tid; idx < CI_ * S_ROWS; idx += 256) {
            int ci = idx / S_ROWS;
            int s  = idx - ci * S_ROWS;
            int qg = q_lo + s;
            float v = 0.0f;
            if (dok && (unsigned)qg < (unsigned)PLANE_Q) {
                int hh = qg / ROWW;
                int ww = qg - hh * ROWW;
                if (ww < NV)
                    v = x[((size_t)(b * CI_ + ci) * NV + dcur) * NV2 + hh * NV + ww];
            }
            scratch[ci * S_STR + s] = __uint_as_float(f2tf32(v));
        }
        __syncthreads();

        #pragma unroll 1
        for (int kh = 0; kh < 3; kh++) {
            #pragma unroll 1
            for (int kw = 0; kw < 3; kw++) {
                const int tap   = dz * 9 + kh * 3 + kw;
                const int sbase = 99 + (kh - 1) * ROWW + (kw - 1) + warp_m;

                // ---- B fragments: 16 coalesced float2 LDG (L1-resident) ----
                float2 bf[4][4];
                const float2* wf = g_wfrag + ((size_t)tap * 8 + (w & 1) * 4) * 128 + lane;
                #pragma unroll
                for (int nt = 0; nt < 4; nt++)
                    #pragma unroll
                    for (int ks = 0; ks < 4; ks++)
                        bf[nt][ks] = wf[(nt * 4 + ks) * 32];

                // ---- A fragments from smem + 32 mma ----
                #pragma unroll
                for (int mt = 0; mt < 2; mt++) {
                    const int mrow = sbase + mt * 16 + g;
                    #pragma unroll
                    for (int ks = 0; ks < 4; ks++) {
                        const int cib = ks * 8 + t;
                        uint32_t a0 = scr_u[cib * S_STR + mrow];
                        uint32_t a1 = scr_u[cib * S_STR + mrow + 8];
                        uint32_t a2 = scr_u[(cib + 4) * S_STR + mrow];
                        uint32_t a3 = scr_u[(cib + 4) * S_STR + mrow + 8];
                        #pragma unroll
                        for (int nt = 0; nt < 4; nt++) {
                            uint32_t b0 = __float_as_uint(bf[nt][ks].x);
                            uint32_t b1 = __float_as_uint(bf[nt][ks].y);
                            asm volatile(
                                "mma.sync.aligned.m16n8k8.row.col.f32.tf32.tf32.f32 "
                                "{%0,%1,%2,%3}, {%4,%5,%6,%7}, {%8,%9}, {%0,%1,%2,%3};\n"
                                : "+f"(acc[mt][nt][0]), "+f"(acc[mt][nt][1]),
                                  "+f"(acc[mt][nt][2]), "+f"(acc[mt][nt][3])
                                : "r"(a0), "r"(a1), "r"(a2), "r"(a3), "r"(b0), "r"(b1));
                        }
                    }
                }
            }
        }
    }

    // ---- epilogue: acc -> smem transpose -> coalesced masked stores ----
    __syncthreads();                 // done with scratch as A source
    float* ep = scratch;             // [m(128)][co] stride 66
    #pragma unroll
    for (int mt = 0; mt < 2; mt++) {
        #pragma unroll
        for (int nt = 0; nt < 4; nt++) {
            int m  = warp_m + mt * 16 + g;
            int co = warp_n + nt * 8 + 2 * t;
            *(float2*)(ep + m * EP_STR + co)       = make_float2(acc[mt][nt][0], acc[mt][nt][1]);
            *(float2*)(ep + (m + 8) * EP_STR + co) = make_float2(acc[mt][nt][2], acc[mt][nt][3]);
        }
    }
    __syncthreads();

    #pragma unroll
    for (int it = 0; it < 4; it++) {
        int m  = it * 32 + lane;
        int q  = q0 + m;
        int hh = q / ROWW;
        int ww = q - hh * ROWW;
        bool ok = (q < PLANE_Q) && (ww < NV);
        float mval = 0.0f;
        int sp = hh * NV + ww;
        if (ok) mval = (float)mask[(size_t)pz * NV2 + sp];
        #pragma unroll
        for (int j = 0; j < 8; j++) {
            int co = w * 8 + j;
            if (ok)
                out[((size_t)(b * CO_ + co) * NV + d) * NV2 + sp] =
                    (ep[m * EP_STR + co] + bs[co]) * mval;
        }
    }
}

// ---------------- launch ----------------
extern "C" void kernel_launch(void* const* d_in, const int* in_sizes, int n_in,
                              void* d_out, int out_size)
{
    const float* x    = (const float*)d_in[0];
    const int*   mask = (const int*)  d_in[1];
    const float* wgt  = (const float*)d_in[2];
    const float* bias = (const float*)d_in[3];
    float* out = (float*)d_out;

    wprep_kernel<<<(27 * 8 * 4 * 32 + 255) / 256, 256>>>(wgt);

    dim3 grid(NTILES, 2 * NV);   // (74, 192)
    conv_mma_kernel<<<grid, 256>>>(x, mask, bias, out);
}